// round 16
// baseline (speedup 1.0000x reference)
#include <cuda_runtime.h>
#include <cstdint>
#include <math.h>

#define N_WL 262144
#define T_REF 273.15f
#define P_REF 101325.0f

#define TILE 128                     // columns per tile
#define NTILES (N_WL / TILE)         // 2048
#define GRID 304                     // persistent: ~2 blocks/SM on 152 SMs
#define NROWS 96                     // 32 cont + 64 mix
#define STAGE (NROWS * TILE)         // floats per stage (12288 = 48KB)
#define SMEM_BYTES (2 * STAGE * 4)   // 98304

// ---- compile-time line constants (LINES / MASS from the problem) ----
__constant__ float c_nu0[10]  = {254.0f, 280.0f, 310.0f, 940.0f, 1130.0f, 1380.0f, 1400.0f, 1600.0f, 2000.0f, 2700.0f};
__constant__ float c_str[10]  = {1.15e-17f, 5e-18f, 1.9e-19f, 2.5e-23f, 8.2e-24f, 1.8e-22f, 3.5e-25f, 7.8e-26f, 4.2e-24f, 1.2e-24f};
__constant__ float c_wid[10]  = {2.0f, 3.0f, 2.5f, 3.0f, 2.5f, 4.0f, 3.0f, 2.5f, 4.0f, 3.5f};
__constant__ float c_tex[10]  = {0.05f, 0.04f, 0.03f, 0.4f, 0.35f, 0.45f, 0.5f, 0.48f, 0.52f, 0.49f};
__constant__ float c_mass[10] = {48.0f, 48.0f, 48.0f, 18.0f, 18.0f, 18.0f, 44.0f, 44.0f, 44.0f, 44.0f};

// Voigt real part w(x,y) with the reference's 3-branch select.
__device__ __forceinline__ float voigt_w(float x, float y) {
    float ax = fabsf(x);
    float s  = ax + y;
    float x2 = x * x;
    float a   = 0.5f + y * y - x2;
    float b   = 2.0f * x * y;
    float num = y * a + x * b;
    float den = a * a + b * b;
    float w   = 0.5641896f * num / den;
    if (s < 15.0f) {
        float ur = y * y - x2;
        float ui = -2.0f * x * y;
        if (ax >= 5.5f) {
            float cr = 1.410474f + 0.5641896f * ur;
            float ci = 0.5641896f * ui;
            float nr = y * cr + x * ci;
            float ni = y * ci - x * cr;
            float dr = 0.75f + ur * (3.0f + ur) - ui * ui;
            float di = ui * (3.0f + 2.0f * ur);
            w = (nr * dr + ni * di) / (dr * dr + di * di);
        } else {
            w = expf(-x2) * cosf(2.0f * x * y) * 0.56418958354f
              + (2.0f * y * 0.31830988618f) * sinf(x2) / (x2 + y * y + 1e-10f);
        }
    }
    return w;
}

__device__ __forceinline__ float siluf(float z)     { return z / (1.0f + expf(-z)); }
__device__ __forceinline__ float softplusf(float z) { return fmaxf(z, 0.0f) + log1pf(expf(-fabsf(z))); }
__device__ __forceinline__ float sigmoidf(float z)  { return 1.0f / (1.0f + expf(-z)); }

__device__ __forceinline__ void cp_async16(unsigned int smem_dst, const void* gmem_src) {
    asm volatile("cp.async.cg.shared.global [%0], [%1], 16;\n"
                 :: "r"(smem_dst), "l"(gmem_src));
}
__device__ __forceinline__ void cp_commit() {
    asm volatile("cp.async.commit_group;\n" ::: "memory");
}
template <int N>
__device__ __forceinline__ void cp_wait() {
    asm volatile("cp.async.wait_group %0;\n" :: "n"(N) : "memory");
}

// Issue one tile's 48KB of weight rows (32 cont + 64 mix) as cp.async.
// 128 threads x 24 chunks of 16B. Chunk c = i*128+t -> row c/32, 16B col (c%32).
__device__ __forceinline__ void prefetch_tile(
    int tile, unsigned int sdst,
    const float* __restrict__ cont_w2, const float* __restrict__ mix_w3)
{
    const int t = threadIdx.x;
    const int colBase = tile * TILE;
    #pragma unroll
    for (int i = 0; i < 24; i++) {
        int c = i * 128 + t;
        int row = c >> 5;                 // 0..95
        int coloff = (c & 31) << 2;       // element offset of 16B chunk
        const float* src = (row < 32)
            ? (cont_w2 + (size_t)row * N_WL + colBase + coloff)
            : (mix_w3 + (size_t)(row - 32) * N_WL + colBase + coloff);
        cp_async16(sdst + (unsigned int)(row * TILE + coloff) * 4u, src);
    }
}

// ---- single persistent kernel ----
// Prologue: commit tile0's async copy, then compute the tiny setup chain
// (line params, h[32], cross[:8], mixing MLP) UNDER the first tile's DRAM
// latency. Mainloop: 2-stage double buffer -- while computing tile i from
// stage s, tile i+1 is already in flight into stage s^1. The DRAM read
// stream never drains for the kernel's lifetime.
__global__ void __launch_bounds__(128, 2) fused_kernel(
    const float* __restrict__ wl,
    const float* __restrict__ Tp, const float* __restrict__ Pp,
    const float* __restrict__ o3p, const float* __restrict__ h2op, const float* __restrict__ co2p,
    const float* __restrict__ mix_w1, const float* __restrict__ mix_b1,
    const float* __restrict__ mix_w2, const float* __restrict__ mix_b2,
    const float* __restrict__ mix_w3, const float* __restrict__ mix_b3,
    const float* __restrict__ cont_w1, const float* __restrict__ cont_b1,
    const float* __restrict__ cont_w2, const float* __restrict__ cont_b2,
    float* __restrict__ out)
{
    extern __shared__ float sw[];      // 2 stages of [96][TILE]
    __shared__ float  sh[32];
    __shared__ float  sm_[64];
    __shared__ float4 sl[10];
    __shared__ float  s_cross8[8];
    __shared__ float  s_mf[10];
    __shared__ float  s_a1[64];

    const int t   = threadIdx.x;
    const int bid = blockIdx.x;
    unsigned int sbase = (unsigned int)__cvta_generic_to_shared(sw);

    // ---- commit first tile immediately (if this block has any work) ----
    const bool has0 = (bid < NTILES);
    if (has0) prefetch_tile(bid, sbase, cont_w2, mix_w3);
    cp_commit();   // group for tile0 (possibly empty; uniform count per thread)

    // ---- setup chain, overlapped with tile0's copy ----
    const float T = *Tp, P = *Pp;
    if (t < 32) {
        const float cH2O = *h2op;
        float feat[5] = { T / (T_REF + 1e-12f), P / (P_REF + 1e-12f), cH2O, 1.0f, 0.0f };
        float z = cont_b1[t];
        #pragma unroll
        for (int i = 0; i < 5; i++) z += feat[i] * cont_w1[i * 32 + t];
        sh[t] = siluf(z);
    }
    if (t < 10) {
        const float cO3 = *o3p, cH2O = *h2op, cCO2 = *co2p;
        float nu0  = c_nu0[t];
        float conc = (t < 3) ? cO3 : ((t < 6) ? cH2O : cCO2);
        float sT   = c_str[t] * powf(T_REF / (T + 1e-12f), c_tex[t]);
        float gL   = c_wid[t] * (P / (P_REF + 1e-12f)) * sqrtf(T_REF / (T + 1e-12f));
        float gD   = nu0 / 299792458.0f * sqrtf(2.0f * 1.380649e-23f * T * 6.02214076e23f / (c_mass[t] + 1e-12f));
        float sigma = gD / (1.1774100226f + 1e-12f);   // sqrt(2*ln2)
        float4 L;
        L.x = nu0;
        L.y = 1.0f / (sigma + 1e-12f);
        L.z = gL / (sigma + 1e-12f);
        L.w = conc * sT / (sigma * 1.77245385091f + 1e-12f);
        sl[t] = L;
    }
    __syncthreads();

    if (t < 8) {
        float wlv = wl[t];
        float cr = 0.0f;
        #pragma unroll
        for (int l = 0; l < 10; l++) {
            float4 L = sl[l];
            cr += L.w * voigt_w((wlv - L.x) * L.y, L.z);
        }
        float z = cont_b2[t];
        #pragma unroll
        for (int k = 0; k < 32; k++) z += sh[k] * cont_w2[k * N_WL + t];
        cr += softplusf(z);
        s_cross8[t] = cr;
    }
    if (t == 0) { s_mf[0] = T / (T_REF + 1e-12f); s_mf[1] = P / (P_REF + 1e-12f); }
    __syncthreads();
    if (t < 8) s_mf[2 + t] = s_cross8[t];
    __syncthreads();

    if (t < 64) {
        float z = mix_b1[t];
        #pragma unroll
        for (int i = 0; i < 10; i++) z += s_mf[i] * mix_w1[i * 64 + t];
        s_a1[t] = siluf(z);
    }
    __syncthreads();
    if (t < 64) {
        float z = mix_b2[t];
        #pragma unroll
        for (int i = 0; i < 64; i++) z += s_a1[i] * mix_w2[i * 64 + t];
        sm_[t] = siluf(z);
    }
    __syncthreads();

    // ---- persistent 2-stage pipeline over tiles bid, bid+GRID, ... ----
    int stage = 0;
    for (int tile = bid; tile < NTILES; tile += GRID) {
        const int j = tile * TILE + t;

        // scalar per-column LDGs issued early (hide under async copies)
        float c  = cont_b2[j];
        float z  = mix_b3[j];
        float wv = wl[j];

        // commit next tile into the other stage before waiting
        const int next = tile + GRID;
        if (next < NTILES) {
            prefetch_tile(next, sbase + (unsigned int)((stage ^ 1) * STAGE) * 4u,
                          cont_w2, mix_w3);
            cp_commit();
        }

        // Voigt while copies fly (pure compute)
        float v = 0.0f;
        #pragma unroll
        for (int l = 0; l < 10; l++) {
            float4 L = sl[l];
            v += L.w * voigt_w((wv - L.x) * L.y, L.z);
        }

        // wait for CURRENT tile only (the next one may stay in flight)
        if (next < NTILES) cp_wait<1>(); else cp_wait<0>();
        __syncthreads();

        const float* buf = sw + stage * STAGE;
        #pragma unroll
        for (int k = 0; k < 32; k++) c += sh[k] * buf[k * TILE + t];
        float cross = v + softplusf(c);

        #pragma unroll
        for (int k = 0; k < 64; k++) z += sm_[k] * buf[(32 + k) * TILE + t];

        out[j] = cross * (1.0f + 0.1f * (sigmoidf(z) - 0.5f));

        __syncthreads();   // all reads of this stage done before it is re-filled
        stage ^= 1;
    }
}

extern "C" void kernel_launch(void* const* d_in, const int* in_sizes, int n_in,
                              void* d_out, int out_size)
{
    const float* wl      = (const float*)d_in[0];
    const float* Tp      = (const float*)d_in[1];
    const float* Pp      = (const float*)d_in[2];
    const float* o3      = (const float*)d_in[3];
    const float* h2o     = (const float*)d_in[4];
    const float* co2     = (const float*)d_in[5];
    const float* mix_w1  = (const float*)d_in[6];
    const float* mix_b1  = (const float*)d_in[7];
    const float* mix_w2  = (const float*)d_in[8];
    const float* mix_b2  = (const float*)d_in[9];
    const float* mix_w3  = (const float*)d_in[10];
    const float* mix_b3  = (const float*)d_in[11];
    const float* cont_w1 = (const float*)d_in[12];
    const float* cont_b1 = (const float*)d_in[13];
    const float* cont_w2 = (const float*)d_in[14];
    const float* cont_b2 = (const float*)d_in[15];
    float* out = (float*)d_out;

    static int smem_set = 0;
    if (!smem_set) {
        cudaFuncSetAttribute(fused_kernel,
                             cudaFuncAttributeMaxDynamicSharedMemorySize, SMEM_BYTES);
        smem_set = 1;
    }

    fused_kernel<<<GRID, 128, SMEM_BYTES>>>(wl, Tp, Pp, o3, h2o, co2,
                                            mix_w1, mix_b1, mix_w2, mix_b2,
                                            mix_w3, mix_b3,
                                            cont_w1, cont_b1, cont_w2, cont_b2,
                                            out);
}